// round 7
// baseline (speedup 1.0000x reference)
#include <cuda_runtime.h>

// Problem constants (fixed by the dataset)
#define NNODES 100000
#define NEDGES 1600000
#define INC    500
#define HID    256
#define OUTC   40
#define KSTEPS 10
#define ALPHA  0.1f
#define LNEPS  1e-5f

// ---------------- scratch (static device globals; no runtime allocation) ----
// Referenced ONLY from device code.
__device__ float g_h1[(size_t)NNODES * HID];   // MLP layer 1 out
__device__ float g_h2[(size_t)NNODES * HID];   // MLP layer 2 out
__device__ float g_h0[(size_t)NNODES * OUTC];  // MLP final (APPNP h0)
__device__ float g_p0[(size_t)NNODES * OUTC];  // ping
__device__ float g_p1[(size_t)NNODES * OUTC];  // pong
__device__ int   g_cnt[NNODES];
__device__ int   g_offs[NNODES + 1];
__device__ int   g_cur[NNODES];
__device__ float g_dinv[NNODES];
__device__ int   g_src[NEDGES];
__device__ float g_wt[NEDGES];

// ---------------------------------------------------------------------------
// Fused GEMM + bias + exact GELU + LayerNorm.
// Block = 32 rows x 256 cols. 256 threads; thread = 4 rows x 8 cols.
// Warp (32 threads) covers one row-group's full 256 columns -> LN via shuffles.
// InSel:  0 -> external pointer A (x),  1 -> g_h1 (device global)
// OutSel: 0 -> g_h1,                    1 -> g_h2
// ---------------------------------------------------------------------------
template <int KDIM, int KC, int InSel, int OutSel>
__global__ void __launch_bounds__(256) mlp_layer_kernel(
    const float* __restrict__ Aext, const float* __restrict__ W,
    const float* __restrict__ bias, const float* __restrict__ gamma,
    const float* __restrict__ beta)
{
    const float* __restrict__ A   = (InSel == 0) ? Aext : (const float*)g_h1;
    float* __restrict__       out = (OutSel == 0) ? g_h1 : g_h2;

    __shared__ float As[32][KC];
    __shared__ float Bs[KC][HID];

    const int tid  = threadIdx.x;
    const int row0 = blockIdx.x * 32;
    const int rg   = tid >> 5;      // 0..7  (row group == warp id)
    const int cg   = tid & 31;      // 0..31 (lane)
    const int r0   = rg * 4;
    const int c0   = cg * 8;

    float acc[4][8];
#pragma unroll
    for (int i = 0; i < 4; ++i)
#pragma unroll
        for (int j = 0; j < 8; ++j) acc[i][j] = 0.0f;

    for (int kt = 0; kt < KDIM / KC; ++kt) {
        const int k0 = kt * KC;
        // A tile: 32 x KC
        for (int idx = tid; idx < 32 * KC; idx += 256) {
            int r = idx / KC, c = idx % KC;
            As[r][c] = A[(size_t)(row0 + r) * KDIM + k0 + c];
        }
        // B tile: KC x 256 (coalesced per row)
#pragma unroll
        for (int kk = 0; kk < KC; ++kk)
            Bs[kk][tid] = W[(size_t)(k0 + kk) * HID + tid];
        __syncthreads();

#pragma unroll
        for (int kk = 0; kk < KC; ++kk) {
            float a0 = As[r0 + 0][kk];
            float a1 = As[r0 + 1][kk];
            float a2 = As[r0 + 2][kk];
            float a3 = As[r0 + 3][kk];
            float4 bx = *(const float4*)&Bs[kk][c0];
            float4 by = *(const float4*)&Bs[kk][c0 + 4];
            float b[8] = {bx.x, bx.y, bx.z, bx.w, by.x, by.y, by.z, by.w};
#pragma unroll
            for (int j = 0; j < 8; ++j) {
                acc[0][j] = fmaf(a0, b[j], acc[0][j]);
                acc[1][j] = fmaf(a1, b[j], acc[1][j]);
                acc[2][j] = fmaf(a2, b[j], acc[2][j]);
                acc[3][j] = fmaf(a3, b[j], acc[3][j]);
            }
        }
        __syncthreads();
    }

    // epilogue: bias + GELU(exact) + LayerNorm
    float4 bi0 = *(const float4*)&bias[c0];
    float4 bi1 = *(const float4*)&bias[c0 + 4];
    float4 ga0 = *(const float4*)&gamma[c0];
    float4 ga1 = *(const float4*)&gamma[c0 + 4];
    float4 be0 = *(const float4*)&beta[c0];
    float4 be1 = *(const float4*)&beta[c0 + 4];
    float bb[8] = {bi0.x, bi0.y, bi0.z, bi0.w, bi1.x, bi1.y, bi1.z, bi1.w};
    float gg[8] = {ga0.x, ga0.y, ga0.z, ga0.w, ga1.x, ga1.y, ga1.z, ga1.w};
    float ee[8] = {be0.x, be0.y, be0.z, be0.w, be1.x, be1.y, be1.z, be1.w};

#pragma unroll
    for (int i = 0; i < 4; ++i) {
        float v[8];
        float s = 0.0f, sq = 0.0f;
#pragma unroll
        for (int j = 0; j < 8; ++j) {
            float t = acc[i][j] + bb[j];
            t = 0.5f * t * (1.0f + erff(t * 0.70710678118654752f));
            v[j] = t;
            s += t;
            sq += t * t;
        }
#pragma unroll
        for (int o = 16; o >= 1; o >>= 1) {
            s  += __shfl_xor_sync(0xffffffffu, s, o);
            sq += __shfl_xor_sync(0xffffffffu, sq, o);
        }
        float mu  = s * (1.0f / HID);
        float var = sq * (1.0f / HID) - mu * mu;
        float rst = rsqrtf(var + LNEPS);
        float o0[4], o1[4];
#pragma unroll
        for (int j = 0; j < 4; ++j) o0[j] = (v[j] - mu) * rst * gg[j] + ee[j];
#pragma unroll
        for (int j = 0; j < 4; ++j) o1[j] = (v[j + 4] - mu) * rst * gg[j + 4] + ee[j + 4];
        float* orow = &out[(size_t)(row0 + r0 + i) * HID + c0];
        *(float4*)&orow[0] = make_float4(o0[0], o0[1], o0[2], o0[3]);
        *(float4*)&orow[4] = make_float4(o1[0], o1[1], o1[2], o1[3]);
    }
}

// ---------------------------------------------------------------------------
// GEMM3: g_h2 [N,256] x W3 [256,40] + b3 -> g_h0. Block = 128 rows.
// Thread = 4 rows x 5 cols (rg = tid>>3, cg = tid&7). Full W3 in smem.
// ---------------------------------------------------------------------------
__global__ void __launch_bounds__(256) gemm3_kernel(
    const float* __restrict__ W, const float* __restrict__ bias)
{
    __shared__ float Ws[HID * OUTC];
    __shared__ float As[128][17];  // pad 17 to kill bank conflicts

    const int tid = threadIdx.x;
    for (int idx = tid; idx < HID * OUTC; idx += 256) Ws[idx] = W[idx];

    const int row0 = blockIdx.x * 128;
    const int rg = tid >> 3;  // 0..31
    const int cg = tid & 7;   // 0..7
    const int r0 = rg * 4;
    const int c0 = cg * 5;

    float acc[4][5];
#pragma unroll
    for (int i = 0; i < 4; ++i)
#pragma unroll
        for (int j = 0; j < 5; ++j) acc[i][j] = 0.0f;

    for (int kt = 0; kt < HID / 16; ++kt) {
        const int k0 = kt * 16;
        __syncthreads();
        for (int idx = tid; idx < 128 * 16; idx += 256) {
            int r = idx >> 4, c = idx & 15;
            int gr = row0 + r;
            As[r][c] = (gr < NNODES) ? g_h2[(size_t)gr * HID + k0 + c] : 0.0f;
        }
        __syncthreads();
#pragma unroll
        for (int kk = 0; kk < 16; ++kk) {
            float a0 = As[r0 + 0][kk];
            float a1 = As[r0 + 1][kk];
            float a2 = As[r0 + 2][kk];
            float a3 = As[r0 + 3][kk];
            const float* wrow = &Ws[(k0 + kk) * OUTC + c0];
#pragma unroll
            for (int j = 0; j < 5; ++j) {
                float w = wrow[j];
                acc[0][j] = fmaf(a0, w, acc[0][j]);
                acc[1][j] = fmaf(a1, w, acc[1][j]);
                acc[2][j] = fmaf(a2, w, acc[2][j]);
                acc[3][j] = fmaf(a3, w, acc[3][j]);
            }
        }
    }
#pragma unroll
    for (int i = 0; i < 4; ++i) {
        int gr = row0 + r0 + i;
        if (gr < NNODES) {
#pragma unroll
            for (int j = 0; j < 5; ++j)
                g_h0[(size_t)gr * OUTC + c0 + j] = acc[i][j] + bias[c0 + j];
        }
    }
}

// ---------------------------------------------------------------------------
// Graph prep kernels. edge_index is INT32 (JAX default x64-disabled: the
// jnp.int64 request silently yields int32). Layout [2, E]: ei[0:E)=src row,
// ei[E:2E)=dst col. Bounds-guarded so bad indices can never trap.
// ---------------------------------------------------------------------------
__global__ void zero_cnt_kernel()
{
    int i = blockIdx.x * blockDim.x + threadIdx.x;
    if (i < NNODES) g_cnt[i] = 0;
}

__global__ void count_kernel(const int* __restrict__ ei)
{
    int e = blockIdx.x * blockDim.x + threadIdx.x;
    if (e < NEDGES) {
        unsigned c = (unsigned)ei[NEDGES + e];
        if (c < NNODES) atomicAdd(&g_cnt[c], 1);
    }
}

__global__ void dinv_kernel()
{
    int i = blockIdx.x * blockDim.x + threadIdx.x;
    if (i < NNODES) g_dinv[i] = rsqrtf(1.0f + (float)g_cnt[i]);  // +1 self loop
}

// single-block exclusive scan over NNODES counts -> offsets (+ cursor copy)
__global__ void scan_kernel()
{
    const int CH = (NNODES + 1023) / 1024;  // 98
    const int t = threadIdx.x;
    const int base = t * CH;
    int s = 0;
    for (int i = 0; i < CH; ++i) {
        int idx = base + i;
        if (idx < NNODES) s += g_cnt[idx];
    }
    __shared__ int sums[1024];
    sums[t] = s;
    __syncthreads();
    for (int off = 1; off < 1024; off <<= 1) {
        int v = (t >= off) ? sums[t - off] : 0;
        __syncthreads();
        sums[t] += v;
        __syncthreads();
    }
    int pre = (t == 0) ? 0 : sums[t - 1];
    for (int i = 0; i < CH; ++i) {
        int idx = base + i;
        if (idx < NNODES) {
            g_offs[idx] = pre;
            g_cur[idx]  = pre;
            pre += g_cnt[idx];
        }
    }
    if (t == 1023) g_offs[NNODES] = sums[1023];
}

__global__ void scatter_kernel(const int* __restrict__ ei)
{
    int e = blockIdx.x * blockDim.x + threadIdx.x;
    if (e < NEDGES) {
        unsigned r = (unsigned)ei[e];
        unsigned c = (unsigned)ei[NEDGES + e];
        if (r < NNODES && c < NNODES) {
            int p = atomicAdd(&g_cur[c], 1);
            g_src[p] = (int)r;
            g_wt[p]  = g_dinv[r] * g_dinv[c];
        }
    }
}

// ---------------------------------------------------------------------------
// APPNP propagation: pull-based, atomic-free. One warp per destination node.
// Lanes map to features: lane -> f, lane<8 -> 32+lane. Self-loop analytic.
// h_next = 0.9 * (sum_e w_e * h_prev[src_e] + dinv^2 * h_prev[i]) + 0.1 * h0
// Buffer selection by iteration index, resolved in DEVICE code:
//   input(it)  = (it==0) ? g_h0 : (it even ? g_p1 : g_p0)
//   output(it) = (it==KSTEPS-1) ? d_out : (it odd ? g_p1 : g_p0)
// ---------------------------------------------------------------------------
__global__ void __launch_bounds__(256) prop_kernel(float* __restrict__ dout, int it)
{
    const float* __restrict__ hprev =
        (it == 0) ? g_h0 : (((it & 1) == 0) ? g_p1 : g_p0);
    float* __restrict__ hnext =
        (it == KSTEPS - 1) ? dout : (((it & 1) != 0) ? g_p1 : g_p0);

    const int warp = (blockIdx.x * blockDim.x + threadIdx.x) >> 5;
    const int lane = threadIdx.x & 31;
    if (warp >= NNODES) return;
    const int node = warp;

    int s = g_offs[node];
    const int e = g_offs[node + 1];
    float acc0 = 0.0f, acc1 = 0.0f;

    // software pipeline: prefetch next edge while accumulating current
    if (s < e) {
        int   u = __ldg(&g_src[s]);
        float w = __ldg(&g_wt[s]);
        for (int i = s + 1; i < e; ++i) {
            int   un = __ldg(&g_src[i]);
            float wn = __ldg(&g_wt[i]);
            const float* r = hprev + (size_t)u * OUTC;
            acc0 = fmaf(w, __ldg(&r[lane]), acc0);
            if (lane < 8) acc1 = fmaf(w, __ldg(&r[32 + lane]), acc1);
            u = un; w = wn;
        }
        const float* r = hprev + (size_t)u * OUTC;
        acc0 = fmaf(w, __ldg(&r[lane]), acc0);
        if (lane < 8) acc1 = fmaf(w, __ldg(&r[32 + lane]), acc1);
    }

    const float d  = g_dinv[node];
    const float sw = d * d;
    const float* rs = hprev + (size_t)node * OUTC;
    const float* r0 = g_h0 + (size_t)node * OUTC;
    float* rn = hnext + (size_t)node * OUTC;

    acc0 = fmaf(sw, __ldg(&rs[lane]), acc0);
    rn[lane] = fmaf(1.0f - ALPHA, acc0, ALPHA * __ldg(&r0[lane]));
    if (lane < 8) {
        acc1 = fmaf(sw, __ldg(&rs[32 + lane]), acc1);
        rn[32 + lane] = fmaf(1.0f - ALPHA, acc1, ALPHA * __ldg(&r0[32 + lane]));
    }
}

// ---------------------------------------------------------------------------
// kernel_launch: ONLY kernel launches. Graph-capturable.
// ---------------------------------------------------------------------------
extern "C" void kernel_launch(void* const* d_in, const int* in_sizes, int n_in,
                              void* d_out, int out_size)
{
    const float* x   = (const float*)d_in[0];
    const int*   ei  = (const int*)d_in[1];   // int32! (JAX x64 disabled)
    const float* W1  = (const float*)d_in[2];
    const float* b1  = (const float*)d_in[3];
    const float* g1  = (const float*)d_in[4];
    const float* be1 = (const float*)d_in[5];
    const float* W2  = (const float*)d_in[6];
    const float* b2  = (const float*)d_in[7];
    const float* g2  = (const float*)d_in[8];
    const float* be2 = (const float*)d_in[9];
    const float* W3  = (const float*)d_in[10];
    const float* b3  = (const float*)d_in[11];
    float*       out = (float*)d_out;

    // --- MLP ---
    mlp_layer_kernel<INC, 20, 0, 0><<<NNODES / 32, 256>>>(x, W1, b1, g1, be1);
    mlp_layer_kernel<HID, 16, 1, 1><<<NNODES / 32, 256>>>(nullptr, W2, b2, g2, be2);
    gemm3_kernel<<<(NNODES + 127) / 128, 256>>>(W3, b3);

    // --- graph prep (per launch; amortized over K propagation steps) ---
    zero_cnt_kernel<<<(NNODES + 255) / 256, 256>>>();
    count_kernel<<<(NEDGES + 255) / 256, 256>>>(ei);
    dinv_kernel<<<(NNODES + 255) / 256, 256>>>();
    scan_kernel<<<1, 1024>>>();
    scatter_kernel<<<(NEDGES + 255) / 256, 256>>>(ei);

    // --- APPNP: K steps, ping-pong inside the kernel; last writes d_out ---
    for (int it = 0; it < KSTEPS; ++it)
        prop_kernel<<<(NNODES * 32 + 255) / 256, 256>>>(out, it);
}

// round 12
// speedup vs baseline: 1.3064x; 1.3064x over previous
#include <cuda_runtime.h>
#include <cuda_bf16.h>
#include <cstdint>

// Problem constants (fixed by the dataset)
#define NNODES 100000
#define NEDGES 1600000
#define INC    500
#define HID    256
#define OUTC   40
#define KSTEPS 10
#define ALPHA  0.1f
#define LNEPS  1e-5f

// ---------------- scratch (static device globals; no runtime allocation) ----
__device__ float g_h1[(size_t)NNODES * HID];   // MLP layer 1 out
__device__ float g_h2[(size_t)NNODES * HID];   // MLP layer 2 out
__device__ float g_h0[(size_t)NNODES * OUTC];  // MLP final (APPNP h0)
__device__ float g_p0[(size_t)NNODES * OUTC];  // ping
__device__ float g_p1[(size_t)NNODES * OUTC];  // pong
__device__ int   g_cnt[NNODES];
__device__ int   g_offs[NNODES + 1];
__device__ int   g_cur[NNODES];
__device__ float g_dinv[NNODES];
__device__ int   g_src[NEDGES];
__device__ float g_wt[NEDGES];

__device__ __forceinline__ float gelu_f(float t) {
    return 0.5f * t * (1.0f + erff(t * 0.70710678118654752f));
}

// HMMA m16n8k16 bf16 x bf16 -> fp32 accumulate (base-target legal, no tcgen05)
__device__ __forceinline__ void mma16816(float* d, const uint32_t* a,
                                         const uint32_t* b)
{
    asm volatile(
        "mma.sync.aligned.m16n8k16.row.col.f32.bf16.bf16.f32 "
        "{%0,%1,%2,%3}, {%4,%5,%6,%7}, {%8,%9}, {%0,%1,%2,%3};"
        : "+f"(d[0]), "+f"(d[1]), "+f"(d[2]), "+f"(d[3])
        : "r"(a[0]), "r"(a[1]), "r"(a[2]), "r"(a[3]), "r"(b[0]), "r"(b[1]));
}

// fp32 -> (hi, lo) bf16 pair, packed 2-wide along k (low half = lower k)
__device__ __forceinline__ void split_pack(float v0, float v1,
                                           uint32_t& ph, uint32_t& pl)
{
    __nv_bfloat16 h0 = __float2bfloat16(v0);
    __nv_bfloat16 h1 = __float2bfloat16(v1);
    __nv_bfloat16 l0 = __float2bfloat16(v0 - __bfloat162float(h0));
    __nv_bfloat16 l1 = __float2bfloat16(v1 - __bfloat162float(h1));
    ph = ((uint32_t)__bfloat16_as_ushort(h1) << 16) | __bfloat16_as_ushort(h0);
    pl = ((uint32_t)__bfloat16_as_ushort(l1) << 16) | __bfloat16_as_ushort(l0);
}

// ===========================================================================
// bf16-split mma.sync MLP layer: out = LayerNorm(GELU(A @ W + b)).
// CTA: 64 rows x 256 cols, 8 warps in 2(M) x 4(N); warp tile 32 x 64.
// K chunk = 32 (two m16n8k16 steps). D += Ah*Bh + Ah*Bl + Al*Bh (fp32 acc).
// InSel: 0 -> Aext (x), 1 -> g_h1.  OutSel: 0 -> g_h1, 1 -> g_h2.
// ===========================================================================
template <int KDIM, int InSel, int OutSel>
__global__ void __launch_bounds__(256) mlp_mma_kernel(
    const float* __restrict__ Aext, const float* __restrict__ W,
    const float* __restrict__ bias, const float* __restrict__ gamma,
    const float* __restrict__ beta)
{
    constexpr int NCH = (KDIM + 31) / 32;
    const float* __restrict__ A   = (InSel == 0) ? Aext : (const float*)g_h1;
    float* __restrict__       out = (OutSel == 0) ? g_h1 : g_h2;

    // pair-packed tiles (u32 = 2 bf16 along k), pad 18 to soften conflicts
    __shared__ uint32_t sAh[64][18], sAl[64][18];
    __shared__ uint32_t sBh[256][18], sBl[256][18];

    const int tid  = threadIdx.x;
    const int wid  = tid >> 5;
    const int lane = tid & 31;
    const int g    = lane >> 2;     // 0..7
    const int tig  = lane & 3;      // 0..3
    const int wm   = wid >> 2;      // 0..1  (M warp)
    const int wn   = wid & 3;       // 0..3  (N warp)
    const int row0 = blockIdx.x * 64;

    float acc[2][8][4];
#pragma unroll
    for (int mt = 0; mt < 2; ++mt)
#pragma unroll
        for (int nt = 0; nt < 8; ++nt)
#pragma unroll
            for (int j = 0; j < 4; ++j) acc[mt][nt][j] = 0.0f;

    for (int c = 0; c < NCH; ++c) {
        const int k0 = c * 32;
        // ---- A tile: 64 rows x 16 k-pairs ----
#pragma unroll
        for (int idx = tid; idx < 64 * 16; idx += 256) {
            const int r = idx >> 4, p = idx & 15;
            const int k = k0 + 2 * p;
            const int gr = row0 + r;
            float v0 = 0.0f, v1 = 0.0f;
            if (gr < NNODES) {
                if (k < KDIM)     v0 = __ldg(&A[(size_t)gr * KDIM + k]);
                if (k + 1 < KDIM) v1 = __ldg(&A[(size_t)gr * KDIM + k + 1]);
            }
            split_pack(v0, v1, sAh[r][p], sAl[r][p]);
        }
        // ---- B tile: B[n][kpair] from W[k][n], 256 n x 16 pairs ----
#pragma unroll
        for (int idx = tid; idx < 16 * 256; idx += 256) {
            const int p = idx >> 8, n = idx & 255;
            const int k = k0 + 2 * p;
            float v0 = (k < KDIM)     ? __ldg(&W[(size_t)k * HID + n])       : 0.0f;
            float v1 = (k + 1 < KDIM) ? __ldg(&W[(size_t)(k + 1) * HID + n]) : 0.0f;
            split_pack(v0, v1, sBh[n][p], sBl[n][p]);
        }
        __syncthreads();

#pragma unroll
        for (int s = 0; s < 2; ++s) {
            const int pb = s * 8;
            uint32_t ah[2][4], al[2][4];
#pragma unroll
            for (int mt = 0; mt < 2; ++mt) {
                const int rb = wm * 32 + mt * 16;
                ah[mt][0] = sAh[rb + g][pb + tig];
                ah[mt][1] = sAh[rb + g + 8][pb + tig];
                ah[mt][2] = sAh[rb + g][pb + tig + 4];
                ah[mt][3] = sAh[rb + g + 8][pb + tig + 4];
                al[mt][0] = sAl[rb + g][pb + tig];
                al[mt][1] = sAl[rb + g + 8][pb + tig];
                al[mt][2] = sAl[rb + g][pb + tig + 4];
                al[mt][3] = sAl[rb + g + 8][pb + tig + 4];
            }
#pragma unroll
            for (int nt = 0; nt < 8; ++nt) {
                const int nb = wn * 64 + nt * 8 + g;
                uint32_t bh[2] = { sBh[nb][pb + tig], sBh[nb][pb + tig + 4] };
                uint32_t bl[2] = { sBl[nb][pb + tig], sBl[nb][pb + tig + 4] };
#pragma unroll
                for (int mt = 0; mt < 2; ++mt) {
                    mma16816(acc[mt][nt], ah[mt], bh);
                    mma16816(acc[mt][nt], ah[mt], bl);
                    mma16816(acc[mt][nt], al[mt], bh);
                }
            }
        }
        __syncthreads();
    }

    // ---- epilogue: bias + exact GELU (in place) + per-row partial sums ----
    float s[2][2] = {{0.f, 0.f}, {0.f, 0.f}};
    float q[2][2] = {{0.f, 0.f}, {0.f, 0.f}};
#pragma unroll
    for (int mt = 0; mt < 2; ++mt)
#pragma unroll
        for (int nt = 0; nt < 8; ++nt)
#pragma unroll
            for (int h = 0; h < 2; ++h)
#pragma unroll
                for (int j = 0; j < 2; ++j) {
                    const int n = wn * 64 + nt * 8 + tig * 2 + j;
                    float t = gelu_f(acc[mt][nt][2 * h + j] + __ldg(&bias[n]));
                    acc[mt][nt][2 * h + j] = t;
                    s[mt][h] += t;
                    q[mt][h] += t * t;
                }
#pragma unroll
    for (int mt = 0; mt < 2; ++mt)
#pragma unroll
        for (int h = 0; h < 2; ++h) {
            s[mt][h] += __shfl_xor_sync(0xffffffffu, s[mt][h], 1);
            s[mt][h] += __shfl_xor_sync(0xffffffffu, s[mt][h], 2);
            q[mt][h] += __shfl_xor_sync(0xffffffffu, q[mt][h], 1);
            q[mt][h] += __shfl_xor_sync(0xffffffffu, q[mt][h], 2);
        }

    // cross-warp (4 N-warps) row reduction through reused smem
    float* ps = (float*)sAh;        // [64 rows][4 warps]
    float* pq = ps + 256;
    if (tig == 0) {
#pragma unroll
        for (int mt = 0; mt < 2; ++mt)
#pragma unroll
            for (int h = 0; h < 2; ++h) {
                const int row = wm * 32 + mt * 16 + h * 8 + g;
                ps[row * 4 + wn] = s[mt][h];
                pq[row * 4 + wn] = q[mt][h];
            }
    }
    __syncthreads();

#pragma unroll
    for (int mt = 0; mt < 2; ++mt)
#pragma unroll
        for (int h = 0; h < 2; ++h) {
            const int row = wm * 32 + mt * 16 + h * 8 + g;
            const int gr  = row0 + row;
            const float st = ps[row * 4 + 0] + ps[row * 4 + 1] +
                             ps[row * 4 + 2] + ps[row * 4 + 3];
            const float qt = pq[row * 4 + 0] + pq[row * 4 + 1] +
                             pq[row * 4 + 2] + pq[row * 4 + 3];
            const float mu  = st * (1.0f / HID);
            const float var = qt * (1.0f / HID) - mu * mu;
            const float rst = rsqrtf(var + LNEPS);
            if (gr < NNODES) {
#pragma unroll
                for (int nt = 0; nt < 8; ++nt) {
                    const int n0 = wn * 64 + nt * 8 + tig * 2;
                    float y0 = (acc[mt][nt][2 * h + 0] - mu) * rst *
                                   __ldg(&gamma[n0]) + __ldg(&beta[n0]);
                    float y1 = (acc[mt][nt][2 * h + 1] - mu) * rst *
                                   __ldg(&gamma[n0 + 1]) + __ldg(&beta[n0 + 1]);
                    *(float2*)&out[(size_t)gr * HID + n0] = make_float2(y0, y1);
                }
            }
        }
}

// ---------------------------------------------------------------------------
// GEMM3: g_h2 [N,256] x W3 [256,40] + b3 -> g_h0. Block = 128 rows.
// ---------------------------------------------------------------------------
__global__ void __launch_bounds__(256) gemm3_kernel(
    const float* __restrict__ W, const float* __restrict__ bias)
{
    __shared__ float Ws[HID * OUTC];
    __shared__ float As[128][17];

    const int tid = threadIdx.x;
    for (int idx = tid; idx < HID * OUTC; idx += 256) Ws[idx] = W[idx];

    const int row0 = blockIdx.x * 128;
    const int rg = tid >> 3;
    const int cg = tid & 7;
    const int r0 = rg * 4;
    const int c0 = cg * 5;

    float acc[4][5];
#pragma unroll
    for (int i = 0; i < 4; ++i)
#pragma unroll
        for (int j = 0; j < 5; ++j) acc[i][j] = 0.0f;

    for (int kt = 0; kt < HID / 16; ++kt) {
        const int k0 = kt * 16;
        __syncthreads();
        for (int idx = tid; idx < 128 * 16; idx += 256) {
            int r = idx >> 4, c = idx & 15;
            int gr = row0 + r;
            As[r][c] = (gr < NNODES) ? g_h2[(size_t)gr * HID + k0 + c] : 0.0f;
        }
        __syncthreads();
#pragma unroll
        for (int kk = 0; kk < 16; ++kk) {
            float a0 = As[r0 + 0][kk];
            float a1 = As[r0 + 1][kk];
            float a2 = As[r0 + 2][kk];
            float a3 = As[r0 + 3][kk];
            const float* wrow = &Ws[(k0 + kk) * OUTC + c0];
#pragma unroll
            for (int j = 0; j < 5; ++j) {
                float w = wrow[j];
                acc[0][j] = fmaf(a0, w, acc[0][j]);
                acc[1][j] = fmaf(a1, w, acc[1][j]);
                acc[2][j] = fmaf(a2, w, acc[2][j]);
                acc[3][j] = fmaf(a3, w, acc[3][j]);
            }
        }
    }
#pragma unroll
    for (int i = 0; i < 4; ++i) {
        int gr = row0 + r0 + i;
        if (gr < NNODES) {
#pragma unroll
            for (int j = 0; j < 5; ++j)
                g_h0[(size_t)gr * OUTC + c0 + j] = acc[i][j] + bias[c0 + j];
        }
    }
}

// ---------------------------------------------------------------------------
// Graph prep kernels. edge_index is int32 [2, E]: ei[0:E)=src, ei[E:2E)=dst.
// ---------------------------------------------------------------------------
__global__ void zero_cnt_kernel()
{
    int i = blockIdx.x * blockDim.x + threadIdx.x;
    if (i < NNODES) g_cnt[i] = 0;
}

__global__ void count_kernel(const int* __restrict__ ei)
{
    int e = blockIdx.x * blockDim.x + threadIdx.x;
    if (e < NEDGES) {
        unsigned c = (unsigned)ei[NEDGES + e];
        if (c < NNODES) atomicAdd(&g_cnt[c], 1);
    }
}

__global__ void dinv_kernel()
{
    int i = blockIdx.x * blockDim.x + threadIdx.x;
    if (i < NNODES) g_dinv[i] = rsqrtf(1.0f + (float)g_cnt[i]);
}

__global__ void scan_kernel()
{
    const int CH = (NNODES + 1023) / 1024;
    const int t = threadIdx.x;
    const int base = t * CH;
    int s = 0;
    for (int i = 0; i < CH; ++i) {
        int idx = base + i;
        if (idx < NNODES) s += g_cnt[idx];
    }
    __shared__ int sums[1024];
    sums[t] = s;
    __syncthreads();
    for (int off = 1; off < 1024; off <<= 1) {
        int v = (t >= off) ? sums[t - off] : 0;
        __syncthreads();
        sums[t] += v;
        __syncthreads();
    }
    int pre = (t == 0) ? 0 : sums[t - 1];
    for (int i = 0; i < CH; ++i) {
        int idx = base + i;
        if (idx < NNODES) {
            g_offs[idx] = pre;
            g_cur[idx]  = pre;
            pre += g_cnt[idx];
        }
    }
    if (t == 1023) g_offs[NNODES] = sums[1023];
}

__global__ void scatter_kernel(const int* __restrict__ ei)
{
    int e = blockIdx.x * blockDim.x + threadIdx.x;
    if (e < NEDGES) {
        unsigned r = (unsigned)ei[e];
        unsigned c = (unsigned)ei[NEDGES + e];
        if (r < NNODES && c < NNODES) {
            int p = atomicAdd(&g_cur[c], 1);
            g_src[p] = (int)r;
            g_wt[p]  = g_dinv[r] * g_dinv[c];
        }
    }
}

// ---------------------------------------------------------------------------
// APPNP propagation: pull-based, one warp per destination node.
// ---------------------------------------------------------------------------
__global__ void __launch_bounds__(256) prop_kernel(float* __restrict__ dout, int it)
{
    const float* __restrict__ hprev =
        (it == 0) ? g_h0 : (((it & 1) == 0) ? g_p1 : g_p0);
    float* __restrict__ hnext =
        (it == KSTEPS - 1) ? dout : (((it & 1) != 0) ? g_p1 : g_p0);

    const int warp = (blockIdx.x * blockDim.x + threadIdx.x) >> 5;
    const int lane = threadIdx.x & 31;
    if (warp >= NNODES) return;
    const int node = warp;

    int s = g_offs[node];
    const int e = g_offs[node + 1];
    float acc0 = 0.0f, acc1 = 0.0f;

    if (s < e) {
        int   u = __ldg(&g_src[s]);
        float w = __ldg(&g_wt[s]);
        for (int i = s + 1; i < e; ++i) {
            int   un = __ldg(&g_src[i]);
            float wn = __ldg(&g_wt[i]);
            const float* r = hprev + (size_t)u * OUTC;
            acc0 = fmaf(w, __ldg(&r[lane]), acc0);
            if (lane < 8) acc1 = fmaf(w, __ldg(&r[32 + lane]), acc1);
            u = un; w = wn;
        }
        const float* r = hprev + (size_t)u * OUTC;
        acc0 = fmaf(w, __ldg(&r[lane]), acc0);
        if (lane < 8) acc1 = fmaf(w, __ldg(&r[32 + lane]), acc1);
    }

    const float d  = g_dinv[node];
    const float sw = d * d;
    const float* rs = hprev + (size_t)node * OUTC;
    const float* r0 = g_h0 + (size_t)node * OUTC;
    float* rn = hnext + (size_t)node * OUTC;

    acc0 = fmaf(sw, __ldg(&rs[lane]), acc0);
    rn[lane] = fmaf(1.0f - ALPHA, acc0, ALPHA * __ldg(&r0[lane]));
    if (lane < 8) {
        acc1 = fmaf(sw, __ldg(&rs[32 + lane]), acc1);
        rn[32 + lane] = fmaf(1.0f - ALPHA, acc1, ALPHA * __ldg(&r0[32 + lane]));
    }
}

// ---------------------------------------------------------------------------
// kernel_launch: ONLY kernel launches. Graph-capturable.
// ---------------------------------------------------------------------------
extern "C" void kernel_launch(void* const* d_in, const int* in_sizes, int n_in,
                              void* d_out, int out_size)
{
    const float* x   = (const float*)d_in[0];
    const int*   ei  = (const int*)d_in[1];   // int32 (JAX x64 disabled)
    const float* W1  = (const float*)d_in[2];
    const float* b1  = (const float*)d_in[3];
    const float* g1  = (const float*)d_in[4];
    const float* be1 = (const float*)d_in[5];
    const float* W2  = (const float*)d_in[6];
    const float* b2  = (const float*)d_in[7];
    const float* g2  = (const float*)d_in[8];
    const float* be2 = (const float*)d_in[9];
    const float* W3  = (const float*)d_in[10];
    const float* b3  = (const float*)d_in[11];
    float*       out = (float*)d_out;

    // --- graph prep first (independent; also puts MLP1 at ncu -s 5) ---
    zero_cnt_kernel<<<(NNODES + 255) / 256, 256>>>();
    count_kernel<<<(NEDGES + 255) / 256, 256>>>(ei);
    dinv_kernel<<<(NNODES + 255) / 256, 256>>>();
    scan_kernel<<<1, 1024>>>();
    scatter_kernel<<<(NEDGES + 255) / 256, 256>>>(ei);

    // --- MLP (bf16-split mma.sync) ---
    const int mlp_grid = (NNODES + 63) / 64;
    mlp_mma_kernel<INC, 0, 0><<<mlp_grid, 256>>>(x, W1, b1, g1, be1);
    mlp_mma_kernel<HID, 1, 1><<<mlp_grid, 256>>>(nullptr, W2, b2, g2, be2);
    gemm3_kernel<<<(NNODES + 127) / 128, 256>>>(W3, b3);

    // --- APPNP: K steps, ping-pong; last writes d_out ---
    for (int it = 0; it < KSTEPS; ++it)
        prop_kernel<<<(NNODES * 32 + 255) / 256, 256>>>(out, it);
}

// round 14
// speedup vs baseline: 1.4374x; 1.1003x over previous
#include <cuda_runtime.h>
#include <cuda_bf16.h>
#include <cstdint>

// Problem constants (fixed by the dataset)
#define NNODES 100000
#define NEDGES 1600000
#define INC    500
#define HID    256
#define OUTC   40
#define KSTEPS 10
#define ALPHA  0.1f
#define LNEPS  1e-5f

#define SCAN_NB 98   // ceil(NNODES / 1024)

// ---------------- scratch (static device globals; no runtime allocation) ----
__device__ float g_h1[(size_t)NNODES * HID];   // MLP layer 1 out
__device__ float g_h2[(size_t)NNODES * HID];   // MLP layer 2 out
__device__ float g_h0[(size_t)NNODES * OUTC];  // MLP final (APPNP h0)
__device__ float g_p0[(size_t)NNODES * OUTC];  // ping
__device__ float g_p1[(size_t)NNODES * OUTC];  // pong
__device__ int   g_cnt[NNODES];                // zero at entry (invariant)
__device__ int   g_offs[NNODES + 1];
__device__ int   g_cur[NNODES];
__device__ float g_dinv[NNODES];
__device__ int   g_src[NEDGES];
__device__ float g_wt[NEDGES];
__device__ int   g_bsum[128];
__device__ int   g_boff[128];

__device__ __forceinline__ float gelu_f(float t) {
    return 0.5f * t * (1.0f + erff(t * 0.70710678118654752f));
}

// HMMA m16n8k16 bf16 x bf16 -> fp32 accumulate (base-target legal)
__device__ __forceinline__ void mma16816(float* d, const uint32_t* a,
                                         const uint32_t* b)
{
    asm volatile(
        "mma.sync.aligned.m16n8k16.row.col.f32.bf16.bf16.f32 "
        "{%0,%1,%2,%3}, {%4,%5,%6,%7}, {%8,%9}, {%0,%1,%2,%3};"
        : "+f"(d[0]), "+f"(d[1]), "+f"(d[2]), "+f"(d[3])
        : "r"(a[0]), "r"(a[1]), "r"(a[2]), "r"(a[3]), "r"(b[0]), "r"(b[1]));
}

// fp32 -> (hi, lo) bf16 pair, packed 2-wide along k (low half = lower k)
__device__ __forceinline__ void split_pack(float v0, float v1,
                                           uint32_t& ph, uint32_t& pl)
{
    __nv_bfloat16 h0 = __float2bfloat16(v0);
    __nv_bfloat16 h1 = __float2bfloat16(v1);
    __nv_bfloat16 l0 = __float2bfloat16(v0 - __bfloat162float(h0));
    __nv_bfloat16 l1 = __float2bfloat16(v1 - __bfloat162float(h1));
    ph = ((uint32_t)__bfloat16_as_ushort(h1) << 16) | __bfloat16_as_ushort(h0);
    pl = ((uint32_t)__bfloat16_as_ushort(l1) << 16) | __bfloat16_as_ushort(l0);
}

// ===========================================================================
// bf16-split mma.sync MLP layer: out = LayerNorm(GELU(A @ W + b)).
// CTA: 64 rows x 256 cols, 8 warps in 2(M) x 4(N); warp tile 32 x 64.
// K chunk = 32 (two m16n8k16 steps). D += Ah*Bh + Ah*Bl + Al*Bh (fp32 acc).
// InSel: 0 -> Aext (x), 1 -> g_h1.  OutSel: 0 -> g_h1, 1 -> g_h2.
// ===========================================================================
template <int KDIM, int InSel, int OutSel>
__global__ void __launch_bounds__(256) mlp_mma_kernel(
    const float* __restrict__ Aext, const float* __restrict__ W,
    const float* __restrict__ bias, const float* __restrict__ gamma,
    const float* __restrict__ beta)
{
    constexpr int NCH = (KDIM + 31) / 32;
    const float* __restrict__ A   = (InSel == 0) ? Aext : (const float*)g_h1;
    float* __restrict__       out = (OutSel == 0) ? g_h1 : g_h2;

    __shared__ uint32_t sAh[64][18], sAl[64][18];
    __shared__ uint32_t sBh[256][18], sBl[256][18];

    const int tid  = threadIdx.x;
    const int wid  = tid >> 5;
    const int lane = tid & 31;
    const int g    = lane >> 2;
    const int tig  = lane & 3;
    const int wm   = wid >> 2;
    const int wn   = wid & 3;
    const int row0 = blockIdx.x * 64;

    float acc[2][8][4];
#pragma unroll
    for (int mt = 0; mt < 2; ++mt)
#pragma unroll
        for (int nt = 0; nt < 8; ++nt)
#pragma unroll
            for (int j = 0; j < 4; ++j) acc[mt][nt][j] = 0.0f;

    for (int c = 0; c < NCH; ++c) {
        const int k0 = c * 32;
#pragma unroll
        for (int idx = tid; idx < 64 * 16; idx += 256) {
            const int r = idx >> 4, p = idx & 15;
            const int k = k0 + 2 * p;
            const int gr = row0 + r;
            float v0 = 0.0f, v1 = 0.0f;
            if (gr < NNODES) {
                if (k < KDIM)     v0 = __ldg(&A[(size_t)gr * KDIM + k]);
                if (k + 1 < KDIM) v1 = __ldg(&A[(size_t)gr * KDIM + k + 1]);
            }
            split_pack(v0, v1, sAh[r][p], sAl[r][p]);
        }
#pragma unroll
        for (int idx = tid; idx < 16 * 256; idx += 256) {
            const int p = idx >> 8, n = idx & 255;
            const int k = k0 + 2 * p;
            float v0 = (k < KDIM)     ? __ldg(&W[(size_t)k * HID + n])       : 0.0f;
            float v1 = (k + 1 < KDIM) ? __ldg(&W[(size_t)(k + 1) * HID + n]) : 0.0f;
            split_pack(v0, v1, sBh[n][p], sBl[n][p]);
        }
        __syncthreads();

#pragma unroll
        for (int s = 0; s < 2; ++s) {
            const int pb = s * 8;
            uint32_t ah[2][4], al[2][4];
#pragma unroll
            for (int mt = 0; mt < 2; ++mt) {
                const int rb = wm * 32 + mt * 16;
                ah[mt][0] = sAh[rb + g][pb + tig];
                ah[mt][1] = sAh[rb + g + 8][pb + tig];
                ah[mt][2] = sAh[rb + g][pb + tig + 4];
                ah[mt][3] = sAh[rb + g + 8][pb + tig + 4];
                al[mt][0] = sAl[rb + g][pb + tig];
                al[mt][1] = sAl[rb + g + 8][pb + tig];
                al[mt][2] = sAl[rb + g][pb + tig + 4];
                al[mt][3] = sAl[rb + g + 8][pb + tig + 4];
            }
#pragma unroll
            for (int nt = 0; nt < 8; ++nt) {
                const int nb = wn * 64 + nt * 8 + g;
                uint32_t bh[2] = { sBh[nb][pb + tig], sBh[nb][pb + tig + 4] };
                uint32_t bl[2] = { sBl[nb][pb + tig], sBl[nb][pb + tig + 4] };
#pragma unroll
                for (int mt = 0; mt < 2; ++mt) {
                    mma16816(acc[mt][nt], ah[mt], bh);
                    mma16816(acc[mt][nt], ah[mt], bl);
                    mma16816(acc[mt][nt], al[mt], bh);
                }
            }
        }
        __syncthreads();
    }

    // ---- epilogue: bias + exact GELU (in place) + per-row partial sums ----
    float s[2][2] = {{0.f, 0.f}, {0.f, 0.f}};
    float q[2][2] = {{0.f, 0.f}, {0.f, 0.f}};
#pragma unroll
    for (int mt = 0; mt < 2; ++mt)
#pragma unroll
        for (int nt = 0; nt < 8; ++nt)
#pragma unroll
            for (int h = 0; h < 2; ++h)
#pragma unroll
                for (int j = 0; j < 2; ++j) {
                    const int n = wn * 64 + nt * 8 + tig * 2 + j;
                    float t = gelu_f(acc[mt][nt][2 * h + j] + __ldg(&bias[n]));
                    acc[mt][nt][2 * h + j] = t;
                    s[mt][h] += t;
                    q[mt][h] += t * t;
                }
#pragma unroll
    for (int mt = 0; mt < 2; ++mt)
#pragma unroll
        for (int h = 0; h < 2; ++h) {
            s[mt][h] += __shfl_xor_sync(0xffffffffu, s[mt][h], 1);
            s[mt][h] += __shfl_xor_sync(0xffffffffu, s[mt][h], 2);
            q[mt][h] += __shfl_xor_sync(0xffffffffu, q[mt][h], 1);
            q[mt][h] += __shfl_xor_sync(0xffffffffu, q[mt][h], 2);
        }

    float* ps = (float*)sAh;        // [64 rows][4 warps]
    float* pq = ps + 256;
    if (tig == 0) {
#pragma unroll
        for (int mt = 0; mt < 2; ++mt)
#pragma unroll
            for (int h = 0; h < 2; ++h) {
                const int row = wm * 32 + mt * 16 + h * 8 + g;
                ps[row * 4 + wn] = s[mt][h];
                pq[row * 4 + wn] = q[mt][h];
            }
    }
    __syncthreads();

#pragma unroll
    for (int mt = 0; mt < 2; ++mt)
#pragma unroll
        for (int h = 0; h < 2; ++h) {
            const int row = wm * 32 + mt * 16 + h * 8 + g;
            const int gr  = row0 + row;
            const float st = ps[row * 4 + 0] + ps[row * 4 + 1] +
                             ps[row * 4 + 2] + ps[row * 4 + 3];
            const float qt = pq[row * 4 + 0] + pq[row * 4 + 1] +
                             pq[row * 4 + 2] + pq[row * 4 + 3];
            const float mu  = st * (1.0f / HID);
            const float var = qt * (1.0f / HID) - mu * mu;
            const float rst = rsqrtf(var + LNEPS);
            if (gr < NNODES) {
#pragma unroll
                for (int nt = 0; nt < 8; ++nt) {
                    const int n0 = wn * 64 + nt * 8 + tig * 2;
                    float y0 = (acc[mt][nt][2 * h + 0] - mu) * rst *
                                   __ldg(&gamma[n0]) + __ldg(&beta[n0]);
                    float y1 = (acc[mt][nt][2 * h + 1] - mu) * rst *
                                   __ldg(&gamma[n0 + 1]) + __ldg(&beta[n0 + 1]);
                    *(float2*)&out[(size_t)gr * HID + n0] = make_float2(y0, y1);
                }
            }
        }
}

// ===========================================================================
// GEMM3 via bf16-split mma: g_h0 = g_h2 [N,256] @ W3 [256,40] + b3.
// CTA: 128 rows x 40 cols, 8 M-warps of 16 rows; warp = 16 x 40 (5 n-tiles).
// ===========================================================================
__global__ void __launch_bounds__(256) gemm3_mma_kernel(
    const float* __restrict__ W, const float* __restrict__ bias)
{
    __shared__ uint32_t sAh[128][18], sAl[128][18];
    __shared__ uint32_t sBh[40][18],  sBl[40][18];

    const int tid  = threadIdx.x;
    const int wid  = tid >> 5;
    const int lane = tid & 31;
    const int g    = lane >> 2;
    const int tig  = lane & 3;
    const int row0 = blockIdx.x * 128;

    float acc[5][4];
#pragma unroll
    for (int nt = 0; nt < 5; ++nt)
#pragma unroll
        for (int j = 0; j < 4; ++j) acc[nt][j] = 0.0f;

    for (int c = 0; c < HID / 32; ++c) {
        const int k0 = c * 32;
#pragma unroll
        for (int idx = tid; idx < 128 * 16; idx += 256) {
            const int r = idx >> 4, p = idx & 15;
            const int k = k0 + 2 * p;
            const int gr = row0 + r;
            float v0 = 0.0f, v1 = 0.0f;
            if (gr < NNODES) {
                v0 = g_h2[(size_t)gr * HID + k];
                v1 = g_h2[(size_t)gr * HID + k + 1];
            }
            split_pack(v0, v1, sAh[r][p], sAl[r][p]);
        }
        for (int idx = tid; idx < 40 * 16; idx += 256) {
            const int n = idx >> 4, p = idx & 15;
            const int k = k0 + 2 * p;
            float v0 = __ldg(&W[(size_t)k * OUTC + n]);
            float v1 = __ldg(&W[(size_t)(k + 1) * OUTC + n]);
            split_pack(v0, v1, sBh[n][p], sBl[n][p]);
        }
        __syncthreads();

#pragma unroll
        for (int s = 0; s < 2; ++s) {
            const int pb = s * 8;
            const int rb = wid * 16;
            uint32_t ah[4], al[4];
            ah[0] = sAh[rb + g][pb + tig];
            ah[1] = sAh[rb + g + 8][pb + tig];
            ah[2] = sAh[rb + g][pb + tig + 4];
            ah[3] = sAh[rb + g + 8][pb + tig + 4];
            al[0] = sAl[rb + g][pb + tig];
            al[1] = sAl[rb + g + 8][pb + tig];
            al[2] = sAl[rb + g][pb + tig + 4];
            al[3] = sAl[rb + g + 8][pb + tig + 4];
#pragma unroll
            for (int nt = 0; nt < 5; ++nt) {
                const int nb = nt * 8 + g;
                uint32_t bh[2] = { sBh[nb][pb + tig], sBh[nb][pb + tig + 4] };
                uint32_t bl[2] = { sBl[nb][pb + tig], sBl[nb][pb + tig + 4] };
                mma16816(acc[nt], ah, bh);
                mma16816(acc[nt], ah, bl);
                mma16816(acc[nt], al, bh);
            }
        }
        __syncthreads();
    }

#pragma unroll
    for (int nt = 0; nt < 5; ++nt)
#pragma unroll
        for (int h = 0; h < 2; ++h) {
            const int gr = row0 + wid * 16 + h * 8 + g;
            const int n0 = nt * 8 + tig * 2;
            if (gr < NNODES) {
                float y0 = acc[nt][2 * h + 0] + __ldg(&bias[n0]);
                float y1 = acc[nt][2 * h + 1] + __ldg(&bias[n0 + 1]);
                *(float2*)&g_h0[(size_t)gr * OUTC + n0] = make_float2(y0, y1);
            }
        }
}

// ---------------------------------------------------------------------------
// Graph prep. edge_index int32 [2, E]: ei[0:E)=src, ei[E:2E)=dst.
// g_cnt is zero at entry (zeroed at END of previous launch; device globals
// start zero-initialized).
// ---------------------------------------------------------------------------
__global__ void count_kernel(const int* __restrict__ ei)
{
    int e = blockIdx.x * blockDim.x + threadIdx.x;
    if (e < NEDGES) {
        unsigned c = (unsigned)ei[NEDGES + e];
        if (c < NNODES) atomicAdd(&g_cnt[c], 1);
    }
}

__global__ void dinv_kernel()
{
    int i = blockIdx.x * blockDim.x + threadIdx.x;
    if (i < NNODES) g_dinv[i] = rsqrtf(1.0f + (float)g_cnt[i]);
}

// parallel scan, phase A: per-block sums (1024 elems/block)
__global__ void __launch_bounds__(1024) scanA_kernel()
{
    const int idx = blockIdx.x * 1024 + threadIdx.x;
    int v = (idx < NNODES) ? g_cnt[idx] : 0;
#pragma unroll
    for (int o = 16; o >= 1; o >>= 1) v += __shfl_xor_sync(0xffffffffu, v, o);
    __shared__ int ws[32];
    if ((threadIdx.x & 31) == 0) ws[threadIdx.x >> 5] = v;
    __syncthreads();
    if (threadIdx.x < 32) {
        int t = ws[threadIdx.x];
#pragma unroll
        for (int o = 16; o >= 1; o >>= 1) t += __shfl_xor_sync(0xffffffffu, t, o);
        if (threadIdx.x == 0) g_bsum[blockIdx.x] = t;
    }
}

// phase B: exclusive scan of SCAN_NB block sums (one 128-thread block)
__global__ void scanB_kernel()
{
    const int t = threadIdx.x;
    const int lane = t & 31, w = t >> 5;
    int v = (t < SCAN_NB) ? g_bsum[t] : 0;
    int iv = v;
#pragma unroll
    for (int o = 1; o < 32; o <<= 1) {
        int n = __shfl_up_sync(0xffffffffu, iv, o);
        if (lane >= o) iv += n;
    }
    __shared__ int ws[4];
    if (lane == 31) ws[w] = iv;
    __syncthreads();
    int add = 0;
    for (int i = 0; i < w; ++i) add += ws[i];
    iv += add;
    if (t < SCAN_NB) g_boff[t] = iv - v;       // exclusive prefix
    if (t == SCAN_NB - 1) g_offs[NNODES] = iv; // grand total
}

// phase C: block-local exclusive scan + global offset -> offs, cur
__global__ void __launch_bounds__(1024) scanC_kernel()
{
    const int idx = blockIdx.x * 1024 + threadIdx.x;
    const int lane = threadIdx.x & 31, w = threadIdx.x >> 5;
    int v = (idx < NNODES) ? g_cnt[idx] : 0;
    int iv = v;
#pragma unroll
    for (int o = 1; o < 32; o <<= 1) {
        int n = __shfl_up_sync(0xffffffffu, iv, o);
        if (lane >= o) iv += n;
    }
    __shared__ int ws[32];
    __shared__ int wo[32];
    if (lane == 31) ws[w] = iv;
    __syncthreads();
    if (threadIdx.x < 32) {
        int t2 = ws[threadIdx.x];
        int s2 = t2;
#pragma unroll
        for (int o = 1; o < 32; o <<= 1) {
            int n = __shfl_up_sync(0xffffffffu, s2, o);
            if (lane >= o) s2 += n;
        }
        wo[threadIdx.x] = s2 - t2;  // exclusive warp prefix
    }
    __syncthreads();
    const int ex = g_boff[blockIdx.x] + wo[w] + (iv - v);
    if (idx < NNODES) {
        g_offs[idx] = ex;
        g_cur[idx]  = ex;
    }
}

__global__ void scatter_kernel(const int* __restrict__ ei)
{
    int e = blockIdx.x * blockDim.x + threadIdx.x;
    if (e < NEDGES) {
        unsigned r = (unsigned)ei[e];
        unsigned c = (unsigned)ei[NEDGES + e];
        if (r < NNODES && c < NNODES) {
            int p = atomicAdd(&g_cur[c], 1);
            g_src[p] = (int)r;
            g_wt[p]  = g_dinv[r] * g_dinv[c];
        }
    }
}

// restore the g_cnt==0 invariant for the next launch (runs at END)
__global__ void zero_cnt_kernel()
{
    int i = blockIdx.x * blockDim.x + threadIdx.x;
    if (i < NNODES) g_cnt[i] = 0;
}

// ---------------------------------------------------------------------------
// APPNP propagation: pull-based, one warp per destination node.
// Explicit 1-deep prefetch of the NEXT edge's row values so the L2 gather
// latency overlaps the current fma instead of serializing.
// ---------------------------------------------------------------------------
__global__ void __launch_bounds__(256) prop_kernel(float* __restrict__ dout, int it)
{
    const float* __restrict__ hprev =
        (it == 0) ? g_h0 : (((it & 1) == 0) ? g_p1 : g_p0);
    float* __restrict__ hnext =
        (it == KSTEPS - 1) ? dout : (((it & 1) != 0) ? g_p1 : g_p0);

    const int warp = (blockIdx.x * blockDim.x + threadIdx.x) >> 5;
    const int lane = threadIdx.x & 31;
    if (warp >= NNODES) return;
    const int node = warp;

    const int s = g_offs[node];
    const int e = g_offs[node + 1];
    float acc0 = 0.0f, acc1 = 0.0f;

    if (s < e) {
        float w = __ldg(&g_wt[s]);
        const int u = __ldg(&g_src[s]);
        const float* r = hprev + (size_t)u * OUTC;
        float rv0 = __ldg(&r[lane]);
        float rv1 = (lane < 8) ? __ldg(&r[32 + lane]) : 0.0f;
        for (int i = s + 1; i < e; ++i) {
            const int   un = __ldg(&g_src[i]);
            const float wn = __ldg(&g_wt[i]);
            const float* rn_ = hprev + (size_t)un * OUTC;
            float nv0 = __ldg(&rn_[lane]);
            float nv1 = (lane < 8) ? __ldg(&rn_[32 + lane]) : 0.0f;
            acc0 = fmaf(w, rv0, acc0);
            acc1 = fmaf(w, rv1, acc1);
            w = wn; rv0 = nv0; rv1 = nv1;
        }
        acc0 = fmaf(w, rv0, acc0);
        acc1 = fmaf(w, rv1, acc1);
    }

    const float d  = g_dinv[node];
    const float sw = d * d;
    const float* rs = hprev + (size_t)node * OUTC;
    const float* r0 = g_h0 + (size_t)node * OUTC;
    float* rn = hnext + (size_t)node * OUTC;

    acc0 = fmaf(sw, __ldg(&rs[lane]), acc0);
    rn[lane] = fmaf(1.0f - ALPHA, acc0, ALPHA * __ldg(&r0[lane]));
    if (lane < 8) {
        acc1 = fmaf(sw, __ldg(&rs[32 + lane]), acc1);
        rn[32 + lane] = fmaf(1.0f - ALPHA, acc1, ALPHA * __ldg(&r0[32 + lane]));
    }
}

// ---------------------------------------------------------------------------
// kernel_launch: ONLY kernel launches. Graph-capturable.
// Order puts mlp1 at launch index 5 so ncu -s 5 profiles the mma kernel.
// ---------------------------------------------------------------------------
extern "C" void kernel_launch(void* const* d_in, const int* in_sizes, int n_in,
                              void* d_out, int out_size)
{
    const float* x   = (const float*)d_in[0];
    const int*   ei  = (const int*)d_in[1];   // int32 (JAX x64 disabled)
    const float* W1  = (const float*)d_in[2];
    const float* b1  = (const float*)d_in[3];
    const float* g1  = (const float*)d_in[4];
    const float* be1 = (const float*)d_in[5];
    const float* W2  = (const float*)d_in[6];
    const float* b2  = (const float*)d_in[7];
    const float* g2  = (const float*)d_in[8];
    const float* be2 = (const float*)d_in[9];
    const float* W3  = (const float*)d_in[10];
    const float* b3  = (const float*)d_in[11];
    float*       out = (float*)d_out;

    const int mlp_grid = (NNODES + 63) / 64;

    // --- graph prep (g_cnt starts zero; re-zeroed at end of launch) ---
    count_kernel<<<(NEDGES + 255) / 256, 256>>>(ei);      // 0
    dinv_kernel<<<(NNODES + 255) / 256, 256>>>();         // 1
    scanA_kernel<<<SCAN_NB, 1024>>>();                    // 2
    scanB_kernel<<<1, 128>>>();                           // 3
    scanC_kernel<<<SCAN_NB, 1024>>>();                    // 4
    mlp_mma_kernel<INC, 0, 0><<<mlp_grid, 256>>>(x, W1, b1, g1, be1);  // 5 (ncu)
    scatter_kernel<<<(NEDGES + 255) / 256, 256>>>(ei);    // 6
    mlp_mma_kernel<HID, 1, 1><<<mlp_grid, 256>>>(nullptr, W2, b2, g2, be2);
    gemm3_mma_kernel<<<(NNODES + 127) / 128, 256>>>(W3, b3);

    // --- APPNP: K steps, ping-pong; last writes d_out ---
    for (int it = 0; it < KSTEPS; ++it)
        prop_kernel<<<(NNODES * 32 + 255) / 256, 256>>>(out, it);

    // restore invariant for next launch (touches only g_cnt)
    zero_cnt_kernel<<<(NNODES + 255) / 256, 256>>>();
}

// round 16
// speedup vs baseline: 1.9420x; 1.3510x over previous
#include <cuda_runtime.h>
#include <cuda_bf16.h>
#include <cstdint>

// Problem constants (fixed by the dataset)
#define NNODES 100000
#define NEDGES 1600000
#define INC    500
#define HID    256
#define OUTC   40
#define KSTEPS 10
#define ALPHA  0.1f
#define LNEPS  1e-5f

#define SCAN_NB 98   // ceil(NNODES / 1024)
#define KP1 250      // INC/2 k-pairs
#define KP2 128      // HID/2 k-pairs

// ---------------- scratch (static device globals; no runtime allocation) ----
__device__ float g_h1[(size_t)NNODES * HID];
__device__ float g_h2[(size_t)NNODES * HID];
__device__ float g_h0[(size_t)NNODES * OUTC];
__device__ float g_p0[(size_t)NNODES * OUTC];
__device__ float g_p1[(size_t)NNODES * OUTC];
__device__ int   g_cnt[NNODES];                // zero at entry (invariant)
__device__ int   g_offs[NNODES + 1];
__device__ int   g_cur[NNODES];
__device__ float g_dinv[NNODES];
__device__ long long g_ew[NEDGES];             // packed (wt<<32 | src)
__device__ int   g_bsum[128];
__device__ int   g_boff[128];
// pre-split weights, [kpair][n] packed bf16x2 (hi, lo)
__device__ uint32_t g_w1h[KP1 * HID], g_w1l[KP1 * HID];
__device__ uint32_t g_w2h[KP2 * HID], g_w2l[KP2 * HID];
__device__ uint32_t g_w3h[KP2 * OUTC], g_w3l[KP2 * OUTC];

__device__ __forceinline__ float gelu_f(float t) {
    return 0.5f * t * (1.0f + erff(t * 0.70710678118654752f));
}

// HMMA m16n8k16 bf16 x bf16 -> fp32 accumulate
__device__ __forceinline__ void mma16816(float* d, const uint32_t* a,
                                         const uint32_t* b)
{
    asm volatile(
        "mma.sync.aligned.m16n8k16.row.col.f32.bf16.bf16.f32 "
        "{%0,%1,%2,%3}, {%4,%5,%6,%7}, {%8,%9}, {%0,%1,%2,%3};"
        : "+f"(d[0]), "+f"(d[1]), "+f"(d[2]), "+f"(d[3])
        : "r"(a[0]), "r"(a[1]), "r"(a[2]), "r"(a[3]), "r"(b[0]), "r"(b[1]));
}

__device__ __forceinline__ void split_pack(float v0, float v1,
                                           uint32_t& ph, uint32_t& pl)
{
    __nv_bfloat16 h0 = __float2bfloat16(v0);
    __nv_bfloat16 h1 = __float2bfloat16(v1);
    __nv_bfloat16 l0 = __float2bfloat16(v0 - __bfloat162float(h0));
    __nv_bfloat16 l1 = __float2bfloat16(v1 - __bfloat162float(h1));
    ph = ((uint32_t)__bfloat16_as_ushort(h1) << 16) | __bfloat16_as_ushort(h0);
    pl = ((uint32_t)__bfloat16_as_ushort(l1) << 16) | __bfloat16_as_ushort(l0);
}

// ---------------------------------------------------------------------------
// Pre-split a weight matrix W [2*KP, NDIM] into packed hi/lo [KP][NDIM].
// ---------------------------------------------------------------------------
template <int KP, int NDIM, int Sel>  // Sel: 0->w1, 1->w2, 2->w3
__global__ void wsplit_kernel(const float* __restrict__ W)
{
    uint32_t* __restrict__ oh = (Sel == 0) ? g_w1h : (Sel == 1) ? g_w2h : g_w3h;
    uint32_t* __restrict__ ol = (Sel == 0) ? g_w1l : (Sel == 1) ? g_w2l : g_w3l;
    int idx = blockIdx.x * blockDim.x + threadIdx.x;
    if (idx < KP * NDIM) {
        const int p = idx / NDIM, n = idx % NDIM;
        const float v0 = __ldg(&W[(size_t)(2 * p) * NDIM + n]);
        const float v1 = __ldg(&W[(size_t)(2 * p + 1) * NDIM + n]);
        split_pack(v0, v1, oh[idx], ol[idx]);
    }
}

// ===========================================================================
// bf16-split mma.sync MLP layer: out = LayerNorm(GELU(A @ W + b)).
// CTA: 64 rows x 256 cols, 8 warps in 2(M) x 4(N); warp tile 32 x 64.
// B comes pre-split from g_w{1,2}{h,l} ([kpair][n], coalesced copies).
// ===========================================================================
template <int KDIM, int InSel, int OutSel>
__global__ void __launch_bounds__(256) mlp_mma_kernel(
    const float* __restrict__ Aext,
    const float* __restrict__ bias, const float* __restrict__ gamma,
    const float* __restrict__ beta)
{
    constexpr int NCH = (KDIM + 31) / 32;
    constexpr int KPAIRS = KDIM / 2;
    const float* __restrict__ A   = (InSel == 0) ? Aext : (const float*)g_h1;
    float* __restrict__       out = (OutSel == 0) ? g_h1 : g_h2;
    const uint32_t* __restrict__ Wh = (InSel == 0) ? g_w1h : g_w2h;
    const uint32_t* __restrict__ Wl = (InSel == 0) ? g_w1l : g_w2l;

    __shared__ uint32_t sAh[64][18], sAl[64][18];
    __shared__ uint32_t sBh[256][18], sBl[256][18];

    const int tid  = threadIdx.x;
    const int wid  = tid >> 5;
    const int lane = tid & 31;
    const int g    = lane >> 2;
    const int tig  = lane & 3;
    const int wm   = wid >> 2;
    const int wn   = wid & 3;
    const int row0 = blockIdx.x * 64;

    float acc[2][8][4];
#pragma unroll
    for (int mt = 0; mt < 2; ++mt)
#pragma unroll
        for (int nt = 0; nt < 8; ++nt)
#pragma unroll
            for (int j = 0; j < 4; ++j) acc[mt][nt][j] = 0.0f;

    for (int c = 0; c < NCH; ++c) {
        const int k0 = c * 32;
        const int pb = c * 16;
#pragma unroll
        for (int idx = tid; idx < 64 * 16; idx += 256) {
            const int r = idx >> 4, p = idx & 15;
            const int k = k0 + 2 * p;
            const int gr = row0 + r;
            float v0 = 0.0f, v1 = 0.0f;
            if (gr < NNODES) {
                if (k < KDIM)     v0 = __ldg(&A[(size_t)gr * KDIM + k]);
                if (k + 1 < KDIM) v1 = __ldg(&A[(size_t)gr * KDIM + k + 1]);
            }
            split_pack(v0, v1, sAh[r][p], sAl[r][p]);
        }
#pragma unroll
        for (int idx = tid; idx < 16 * 256; idx += 256) {
            const int p = idx >> 8, n = idx & 255;
            const int gp = pb + p;
            uint32_t vh = 0, vl = 0;
            if (gp < KPAIRS) {
                vh = __ldg(&Wh[(size_t)gp * HID + n]);
                vl = __ldg(&Wl[(size_t)gp * HID + n]);
            }
            sBh[n][p] = vh;
            sBl[n][p] = vl;
        }
        __syncthreads();

#pragma unroll
        for (int s = 0; s < 2; ++s) {
            const int pb2 = s * 8;
            uint32_t ah[2][4], al[2][4];
#pragma unroll
            for (int mt = 0; mt < 2; ++mt) {
                const int rb = wm * 32 + mt * 16;
                ah[mt][0] = sAh[rb + g][pb2 + tig];
                ah[mt][1] = sAh[rb + g + 8][pb2 + tig];
                ah[mt][2] = sAh[rb + g][pb2 + tig + 4];
                ah[mt][3] = sAh[rb + g + 8][pb2 + tig + 4];
                al[mt][0] = sAl[rb + g][pb2 + tig];
                al[mt][1] = sAl[rb + g + 8][pb2 + tig];
                al[mt][2] = sAl[rb + g][pb2 + tig + 4];
                al[mt][3] = sAl[rb + g + 8][pb2 + tig + 4];
            }
#pragma unroll
            for (int nt = 0; nt < 8; ++nt) {
                const int nb = wn * 64 + nt * 8 + g;
                uint32_t bh[2] = { sBh[nb][pb2 + tig], sBh[nb][pb2 + tig + 4] };
                uint32_t bl[2] = { sBl[nb][pb2 + tig], sBl[nb][pb2 + tig + 4] };
#pragma unroll
                for (int mt = 0; mt < 2; ++mt) {
                    mma16816(acc[mt][nt], ah[mt], bh);
                    mma16816(acc[mt][nt], ah[mt], bl);
                    mma16816(acc[mt][nt], al[mt], bh);
                }
            }
        }
        __syncthreads();
    }

    // ---- epilogue: bias + exact GELU (in place) + per-row partial sums ----
    float s[2][2] = {{0.f, 0.f}, {0.f, 0.f}};
    float q[2][2] = {{0.f, 0.f}, {0.f, 0.f}};
#pragma unroll
    for (int mt = 0; mt < 2; ++mt)
#pragma unroll
        for (int nt = 0; nt < 8; ++nt)
#pragma unroll
            for (int h = 0; h < 2; ++h)
#pragma unroll
                for (int j = 0; j < 2; ++j) {
                    const int n = wn * 64 + nt * 8 + tig * 2 + j;
                    float t = gelu_f(acc[mt][nt][2 * h + j] + __ldg(&bias[n]));
                    acc[mt][nt][2 * h + j] = t;
                    s[mt][h] += t;
                    q[mt][h] += t * t;
                }
#pragma unroll
    for (int mt = 0; mt < 2; ++mt)
#pragma unroll
        for (int h = 0; h < 2; ++h) {
            s[mt][h] += __shfl_xor_sync(0xffffffffu, s[mt][h], 1);
            s[mt][h] += __shfl_xor_sync(0xffffffffu, s[mt][h], 2);
            q[mt][h] += __shfl_xor_sync(0xffffffffu, q[mt][h], 1);
            q[mt][h] += __shfl_xor_sync(0xffffffffu, q[mt][h], 2);
        }

    float* ps = (float*)sAh;        // [64 rows][4 warps]
    float* pq = ps + 256;
    if (tig == 0) {
#pragma unroll
        for (int mt = 0; mt < 2; ++mt)
#pragma unroll
            for (int h = 0; h < 2; ++h) {
                const int row = wm * 32 + mt * 16 + h * 8 + g;
                ps[row * 4 + wn] = s[mt][h];
                pq[row * 4 + wn] = q[mt][h];
            }
    }
    __syncthreads();

#pragma unroll
    for (int mt = 0; mt < 2; ++mt)
#pragma unroll
        for (int h = 0; h < 2; ++h) {
            const int row = wm * 32 + mt * 16 + h * 8 + g;
            const int gr  = row0 + row;
            const float st = ps[row * 4 + 0] + ps[row * 4 + 1] +
                             ps[row * 4 + 2] + ps[row * 4 + 3];
            const float qt = pq[row * 4 + 0] + pq[row * 4 + 1] +
                             pq[row * 4 + 2] + pq[row * 4 + 3];
            const float mu  = st * (1.0f / HID);
            const float var = qt * (1.0f / HID) - mu * mu;
            const float rst = rsqrtf(var + LNEPS);
            if (gr < NNODES) {
#pragma unroll
                for (int nt = 0; nt < 8; ++nt) {
                    const int n0 = wn * 64 + nt * 8 + tig * 2;
                    float y0 = (acc[mt][nt][2 * h + 0] - mu) * rst *
                                   __ldg(&gamma[n0]) + __ldg(&beta[n0]);
                    float y1 = (acc[mt][nt][2 * h + 1] - mu) * rst *
                                   __ldg(&gamma[n0 + 1]) + __ldg(&beta[n0 + 1]);
                    *(float2*)&out[(size_t)gr * HID + n0] = make_float2(y0, y1);
                }
            }
        }
}

// ===========================================================================
// GEMM3 via bf16-split mma: g_h0 = g_h2 [N,256] @ W3 [256,40] + b3.
// CTA: 128 rows x 40 cols, 8 M-warps of 16 rows. B pre-split from g_w3*.
// ===========================================================================
__global__ void __launch_bounds__(256) gemm3_mma_kernel(
    const float* __restrict__ bias)
{
    __shared__ uint32_t sAh[128][18], sAl[128][18];
    __shared__ uint32_t sBh[40][18],  sBl[40][18];

    const int tid  = threadIdx.x;
    const int wid  = tid >> 5;
    const int lane = tid & 31;
    const int g    = lane >> 2;
    const int tig  = lane & 3;
    const int row0 = blockIdx.x * 128;

    float acc[5][4];
#pragma unroll
    for (int nt = 0; nt < 5; ++nt)
#pragma unroll
        for (int j = 0; j < 4; ++j) acc[nt][j] = 0.0f;

    for (int c = 0; c < HID / 32; ++c) {
        const int k0 = c * 32;
        const int pb = c * 16;
#pragma unroll
        for (int idx = tid; idx < 128 * 16; idx += 256) {
            const int r = idx >> 4, p = idx & 15;
            const int k = k0 + 2 * p;
            const int gr = row0 + r;
            float v0 = 0.0f, v1 = 0.0f;
            if (gr < NNODES) {
                v0 = g_h2[(size_t)gr * HID + k];
                v1 = g_h2[(size_t)gr * HID + k + 1];
            }
            split_pack(v0, v1, sAh[r][p], sAl[r][p]);
        }
        for (int idx = tid; idx < 40 * 16; idx += 256) {
            const int n = idx / 16, p = idx & 15;
            sBh[n][p] = g_w3h[(size_t)(pb + p) * OUTC + n];
            sBl[n][p] = g_w3l[(size_t)(pb + p) * OUTC + n];
        }
        __syncthreads();

#pragma unroll
        for (int s = 0; s < 2; ++s) {
            const int pb2 = s * 8;
            const int rb = wid * 16;
            uint32_t ah[4], al[4];
            ah[0] = sAh[rb + g][pb2 + tig];
            ah[1] = sAh[rb + g + 8][pb2 + tig];
            ah[2] = sAh[rb + g][pb2 + tig + 4];
            ah[3] = sAh[rb + g + 8][pb2 + tig + 4];
            al[0] = sAl[rb + g][pb2 + tig];
            al[1] = sAl[rb + g + 8][pb2 + tig];
            al[2] = sAl[rb + g][pb2 + tig + 4];
            al[3] = sAl[rb + g + 8][pb2 + tig + 4];
#pragma unroll
            for (int nt = 0; nt < 5; ++nt) {
                const int nb = nt * 8 + g;
                uint32_t bh[2] = { sBh[nb][pb2 + tig], sBh[nb][pb2 + tig + 4] };
                uint32_t bl[2] = { sBl[nb][pb2 + tig], sBl[nb][pb2 + tig + 4] };
                mma16816(acc[nt], ah, bh);
                mma16816(acc[nt], ah, bl);
                mma16816(acc[nt], al, bh);
            }
        }
        __syncthreads();
    }

#pragma unroll
    for (int nt = 0; nt < 5; ++nt)
#pragma unroll
        for (int h = 0; h < 2; ++h) {
            const int gr = row0 + wid * 16 + h * 8 + g;
            const int n0 = nt * 8 + tig * 2;
            if (gr < NNODES) {
                float y0 = acc[nt][2 * h + 0] + __ldg(&bias[n0]);
                float y1 = acc[nt][2 * h + 1] + __ldg(&bias[n0 + 1]);
                *(float2*)&g_h0[(size_t)gr * OUTC + n0] = make_float2(y0, y1);
            }
        }
}

// ---------------------------------------------------------------------------
// Graph prep. edge_index int32 [2, E]: ei[0:E)=src, ei[E:2E)=dst.
// ---------------------------------------------------------------------------
__global__ void count_kernel(const int* __restrict__ ei)
{
    int e = blockIdx.x * blockDim.x + threadIdx.x;
    if (e < NEDGES) {
        unsigned c = (unsigned)ei[NEDGES + e];
        if (c < NNODES) atomicAdd(&g_cnt[c], 1);
    }
}

__global__ void dinv_kernel()
{
    int i = blockIdx.x * blockDim.x + threadIdx.x;
    if (i < NNODES) g_dinv[i] = rsqrtf(1.0f + (float)g_cnt[i]);
}

// parallel scan, phase A: per-block sums (1024 elems/block)
__global__ void __launch_bounds__(1024) scanA_kernel()
{
    const int idx = blockIdx.x * 1024 + threadIdx.x;
    int v = (idx < NNODES) ? g_cnt[idx] : 0;
#pragma unroll
    for (int o = 16; o >= 1; o >>= 1) v += __shfl_xor_sync(0xffffffffu, v, o);
    __shared__ int ws[32];
    if ((threadIdx.x & 31) == 0) ws[threadIdx.x >> 5] = v;
    __syncthreads();
    if (threadIdx.x < 32) {
        int t = ws[threadIdx.x];
#pragma unroll
        for (int o = 16; o >= 1; o >>= 1) t += __shfl_xor_sync(0xffffffffu, t, o);
        if (threadIdx.x == 0) g_bsum[blockIdx.x] = t;
    }
}

// phase B: exclusive scan of SCAN_NB block sums (one 128-thread block)
__global__ void scanB_kernel()
{
    const int t = threadIdx.x;
    const int lane = t & 31, w = t >> 5;
    int v = (t < SCAN_NB) ? g_bsum[t] : 0;
    int iv = v;
#pragma unroll
    for (int o = 1; o < 32; o <<= 1) {
        int n = __shfl_up_sync(0xffffffffu, iv, o);
        if (lane >= o) iv += n;
    }
    __shared__ int ws[4];
    if (lane == 31) ws[w] = iv;
    __syncthreads();
    int add = 0;
    for (int i = 0; i < w; ++i) add += ws[i];
    iv += add;
    if (t < SCAN_NB) g_boff[t] = iv - v;
    if (t == SCAN_NB - 1) g_offs[NNODES] = iv;
}

// phase C: block-local exclusive scan + global offset -> offs, cur
__global__ void __launch_bounds__(1024) scanC_kernel()
{
    const int idx = blockIdx.x * 1024 + threadIdx.x;
    const int lane = threadIdx.x & 31, w = threadIdx.x >> 5;
    int v = (idx < NNODES) ? g_cnt[idx] : 0;
    int iv = v;
#pragma unroll
    for (int o = 1; o < 32; o <<= 1) {
        int n = __shfl_up_sync(0xffffffffu, iv, o);
        if (lane >= o) iv += n;
    }
    __shared__ int ws[32];
    __shared__ int wo[32];
    if (lane == 31) ws[w] = iv;
    __syncthreads();
    if (threadIdx.x < 32) {
        int t2 = ws[threadIdx.x];
        int s2 = t2;
#pragma unroll
        for (int o = 1; o < 32; o <<= 1) {
            int n = __shfl_up_sync(0xffffffffu, s2, o);
            if (lane >= o) s2 += n;
        }
        wo[threadIdx.x] = s2 - t2;
    }
    __syncthreads();
    const int ex = g_boff[blockIdx.x] + wo[w] + (iv - v);
    if (idx < NNODES) {
        g_offs[idx] = ex;
        g_cur[idx]  = ex;
    }
}

__global__ void scatter_kernel(const int* __restrict__ ei)
{
    int e = blockIdx.x * blockDim.x + threadIdx.x;
    if (e < NEDGES) {
        unsigned r = (unsigned)ei[e];
        unsigned c = (unsigned)ei[NEDGES + e];
        if (r < NNODES && c < NNODES) {
            int p = atomicAdd(&g_cur[c], 1);
            const float wt = g_dinv[r] * g_dinv[c];
            g_ew[p] = ((long long)(unsigned long long)__float_as_uint(wt) << 32) |
                      (long long)r;
        }
    }
}

// restore the g_cnt==0 invariant for the next launch (runs at END)
__global__ void zero_cnt_kernel()
{
    int i = blockIdx.x * blockDim.x + threadIdx.x;
    if (i < NNODES) g_cnt[i] = 0;
}

// ---------------------------------------------------------------------------
// APPNP propagation v2: one warp per node, 3 edges per loop step.
// Lanes 0-29 in 3 groups of 10; each group loads one edge's row as 10 float4
// (one LDG.128 issue covers all 3 rows). Edge meta packed (wt<<32|src), one
// LDG.64 per 3 edges + shfl broadcast. Cross-group combine via shfl.
// ---------------------------------------------------------------------------
__global__ void __launch_bounds__(256) prop_kernel(float* __restrict__ dout, int it)
{
    const float4* __restrict__ hp = (const float4*)
        ((it == 0) ? g_h0 : (((it & 1) == 0) ? g_p1 : g_p0));
    float4* __restrict__ hn = (float4*)
        ((it == KSTEPS - 1) ? dout : (((it & 1) != 0) ? g_p1 : g_p0));
    const float4* __restrict__ h04 = (const float4*)g_h0;

    const int warp = (blockIdx.x * blockDim.x + threadIdx.x) >> 5;
    const int lane = threadIdx.x & 31;
    if (warp >= NNODES) return;
    const int node = warp;

    const int s = g_offs[node];
    const int e = g_offs[node + 1];

    const int grp  = lane / 10;            // 0..2 active, 3 for lanes 30-31
    const int fl   = lane - grp * 10;      // 0..9
    const bool lact = (lane < 30);
    const int bsrc = (grp < 3) ? grp : 0;  // shfl source for meta

    float4 acc = make_float4(0.f, 0.f, 0.f, 0.f);

    for (int i = s; i < e; i += 3) {
        long long m = 0;
        if (lane < 3 && (i + lane) < e) m = __ldg(&g_ew[i + lane]);
        const long long mg = __shfl_sync(0xffffffffu, m, bsrc);
        const int   u = (int)(unsigned)((unsigned long long)mg & 0xffffffffull);
        const float w = __uint_as_float((unsigned)((unsigned long long)mg >> 32));
        if (lact && (i + grp) < e) {
            const float4 v = __ldg(&hp[(size_t)u * 10 + fl]);
            acc.x = fmaf(w, v.x, acc.x);
            acc.y = fmaf(w, v.y, acc.y);
            acc.z = fmaf(w, v.z, acc.z);
            acc.w = fmaf(w, v.w, acc.w);
        }
    }

    // combine the 3 groups into lanes 0-9
    const float t1x = __shfl_sync(0xffffffffu, acc.x, lane + 10);
    const float t1y = __shfl_sync(0xffffffffu, acc.y, lane + 10);
    const float t1z = __shfl_sync(0xffffffffu, acc.z, lane + 10);
    const float t1w = __shfl_sync(0xffffffffu, acc.w, lane + 10);
    const float t2x = __shfl_sync(0xffffffffu, acc.x, lane + 20);
    const float t2y = __shfl_sync(0xffffffffu, acc.y, lane + 20);
    const float t2z = __shfl_sync(0xffffffffu, acc.z, lane + 20);
    const float t2w = __shfl_sync(0xffffffffu, acc.w, lane + 20);

    if (lane < 10) {
        acc.x += t1x + t2x;
        acc.y += t1y + t2y;
        acc.z += t1z + t2z;
        acc.w += t1w + t2w;

        const float d  = g_dinv[node];
        const float sw = d * d;
        const float4 sv = __ldg(&hp[(size_t)node * 10 + lane]);
        const float4 hv = __ldg(&h04[(size_t)node * 10 + lane]);
        float4 o;
        o.x = fmaf(1.0f - ALPHA, fmaf(sw, sv.x, acc.x), ALPHA * hv.x);
        o.y = fmaf(1.0f - ALPHA, fmaf(sw, sv.y, acc.y), ALPHA * hv.y);
        o.z = fmaf(1.0f - ALPHA, fmaf(sw, sv.z, acc.z), ALPHA * hv.z);
        o.w = fmaf(1.0f - ALPHA, fmaf(sw, sv.w, acc.w), ALPHA * hv.w);
        hn[(size_t)node * 10 + lane] = o;
    }
}

// ---------------------------------------------------------------------------
// kernel_launch: ONLY kernel launches. Graph-capturable.
// ---------------------------------------------------------------------------
extern "C" void kernel_launch(void* const* d_in, const int* in_sizes, int n_in,
                              void* d_out, int out_size)
{
    const float* x   = (const float*)d_in[0];
    const int*   ei  = (const int*)d_in[1];   // int32 (JAX x64 disabled)
    const float* W1  = (const float*)d_in[2];
    const float* b1  = (const float*)d_in[3];
    const float* g1  = (const float*)d_in[4];
    const float* be1 = (const float*)d_in[5];
    const float* W2  = (const float*)d_in[6];
    const float* b2  = (const float*)d_in[7];
    const float* g2  = (const float*)d_in[8];
    const float* be2 = (const float*)d_in[9];
    const float* W3  = (const float*)d_in[10];
    const float* b3  = (const float*)d_in[11];
    float*       out = (float*)d_out;

    const int mlp_grid = (NNODES + 63) / 64;

    // --- graph prep + weight pre-split ---
    count_kernel<<<(NEDGES + 255) / 256, 256>>>(ei);                  // 0
    wsplit_kernel<KP1, HID, 0><<<(KP1 * HID + 255) / 256, 256>>>(W1); // 1
    wsplit_kernel<KP2, HID, 1><<<(KP2 * HID + 255) / 256, 256>>>(W2); // 2
    wsplit_kernel<KP2, OUTC, 2><<<(KP2 * OUTC + 255) / 256, 256>>>(W3); // 3
    dinv_kernel<<<(NNODES + 255) / 256, 256>>>();                     // 4
    mlp_mma_kernel<INC, 0, 0><<<mlp_grid, 256>>>(x, b1, g1, be1);     // 5 (ncu)
    scanA_kernel<<<SCAN_NB, 1024>>>();
    scanB_kernel<<<1, 128>>>();
    scanC_kernel<<<SCAN_NB, 1024>>>();
    scatter_kernel<<<(NEDGES + 255) / 256, 256>>>(ei);
    mlp_mma_kernel<HID, 1, 1><<<mlp_grid, 256>>>(nullptr, b2, g2, be2);
    gemm3_mma_kernel<<<(NNODES + 127) / 128, 256>>>(b3);

    // --- APPNP: K steps, ping-pong; last writes d_out ---
    for (int it = 0; it < KSTEPS; ++it)
        prop_kernel<<<(NNODES * 32 + 255) / 256, 256>>>(out, it);

    // restore invariant for next launch
    zero_cnt_kernel<<<(NNODES + 255) / 256, 256>>>();
}